// round 7
// baseline (speedup 1.0000x reference)
#include <cuda_runtime.h>
#include <cuda_bf16.h>
#include <cstdint>
#include <math.h>

#define Bn    4
#define SEQ   4096
#define Ein   2048
#define HD    2048
#define HEADS 16
#define DHd   128
#define MR    (Bn * SEQ)      // 16384
#define SPLITS 8

// ---------------------------------------------------------------------------
// PTX helpers (base-target safe: sm_80+ instructions only)
// ---------------------------------------------------------------------------
__device__ __forceinline__ uint32_t smem_u32(const void* p) {
    uint32_t a;
    asm("{ .reg .u64 t; cvta.to.shared.u64 t, %1; cvt.u32.u64 %0, t; }" : "=r"(a) : "l"(p));
    return a;
}

#define CP16(dst, src) \
    asm volatile("cp.async.cg.shared.global [%0], [%1], 16;" :: "r"(dst), "l"(src) : "memory")
#define CP_COMMIT() asm volatile("cp.async.commit_group;" ::: "memory")
#define CP_WAIT(n)  asm volatile("cp.async.wait_group %0;" :: "n"(n) : "memory")

#define LDMX4(r, addr) \
    asm volatile("ldmatrix.sync.aligned.m8n8.x4.shared.b16 {%0,%1,%2,%3}, [%4];" \
        : "=r"((r)[0]), "=r"((r)[1]), "=r"((r)[2]), "=r"((r)[3]) : "r"(addr))

#define MMA_BF16(d, a, b0v, b1v) \
    asm volatile("mma.sync.aligned.m16n8k16.row.col.f32.bf16.bf16.f32 " \
        "{%0,%1,%2,%3}, {%4,%5,%6,%7}, {%8,%9}, {%0,%1,%2,%3};" \
        : "+f"((d)[0]), "+f"((d)[1]), "+f"((d)[2]), "+f"((d)[3]) \
        : "r"((a)[0]), "r"((a)[1]), "r"((a)[2]), "r"((a)[3]), "r"(b0v), "r"(b1v))

// ---------------------------------------------------------------------------
// scratch (device globals; no allocation allowed)
// ---------------------------------------------------------------------------
__device__ float g_q [MR * HD];
__device__ float g_v [MR * HD];
__device__ float g_u [MR * HD];
__device__ float g_o [MR * HD];
__device__ float g_kv[SPLITS * Bn * HEADS * DHd * DHd];
__device__ __nv_bfloat16 g_xh [MR * Ein];
__device__ __nv_bfloat16 g_xl [MR * Ein];
__device__ __nv_bfloat16 g_lnh[MR * HD];
__device__ __nv_bfloat16 g_lnl[MR * HD];
__device__ __nv_bfloat16 g_wqkh[HD * Ein], g_wqkl[HD * Ein];   // [N][K] transposed
__device__ __nv_bfloat16 g_wvh [HD * Ein], g_wvl [HD * Ein];
__device__ __nv_bfloat16 g_wuh [HD * Ein], g_wul [HD * Ein];
__device__ __nv_bfloat16 g_woh [Ein * HD], g_wol [Ein * HD];

// ---------------------------------------------------------------------------
// bf16 3-product GEMM: C = act( (Ah+Al)@(Bh+Bl)^T + bias ), dropping Al*Bl.
// BM=128 BN=128 BK=32, 3-stage cp.async ring, 8 warps (2m x 4n), warp 64x32.
// Stage = 32KB (Ah|Al|Bh|Bl of 8KB), 96KB smem -> 2 CTAs/SM.
// Swizzle for 64B rows: chunk c ^= (row>>1)&3  (conflict-free ldmatrix+STS).
// ---------------------------------------------------------------------------
#define BM 128
#define BN 128
#define BK 32
#define STAGES 3
#define OFF_AH 0
#define OFF_AL 8192
#define OFF_BH 16384
#define OFF_BL 24576
#define STG_BYTES 32768
#define GEMM_SMEM (STAGES * STG_BYTES)           // 98304
#define NIT (2048 / BK)                          // 64

template<int ACT>   // 0 none, 1 elu, 2 silu
__global__ void __launch_bounds__(256, 2) gemm_bf16_3p(
    const __nv_bfloat16* __restrict__ Ah, const __nv_bfloat16* __restrict__ Al,
    const __nv_bfloat16* __restrict__ Bh, const __nv_bfloat16* __restrict__ Bl,
    const float* __restrict__ bias, float* __restrict__ C)
{
    extern __shared__ char smem[];
    const uint32_t sb = smem_u32(smem);
    const int tid = threadIdx.x;
    const int m0 = blockIdx.y * BM;
    const int n0 = blockIdx.x * BN;

    const int lane = tid & 31, w = tid >> 5;
    const int wm = (w >> 2) * 64;        // warp m offset
    const int wn = (w & 3) * 32;         // warp n offset
    const int mi = lane >> 3, rowin = lane & 7;

    // A frag: matrices {m0-7/k0-7, m8-15/k0-7, m0-7/k8-15, m8-15/k8-15}
    const int au = mi >> 1, aro = (mi & 1) << 3;
    uint32_t aoff[4]; int arx[4];
#pragma unroll
    for (int mt = 0; mt < 4; mt++) {
        int r = wm + mt * 16 + aro + rowin;
        aoff[mt] = r * 64;
        arx[mt] = (r >> 1) & 3;
    }
    // B frag: matrices {n0-7/k0-7, n0-7/k8-15, n8-15/k0-7, n8-15/k8-15}
    const int bu = mi & 1, bro = (mi >> 1) << 3;
    uint32_t boff[2]; int brx[2];
#pragma unroll
    for (int p = 0; p < 2; p++) {
        int r = wn + p * 16 + bro + rowin;
        boff[p] = OFF_BH + r * 64;
        brx[p] = (r >> 1) & 3;
    }

    // per-thread cp.async indices: row lr & lr+64, 16B chunk lu
    const int lr = tid >> 2, lu = tid & 3;
    const uint32_t sw0 = (uint32_t)(lr * 64 + ((lu ^ ((lr >> 1) & 3)) << 4));  // +4096 for row lr+64
    const __nv_bfloat16* Ahp = Ah + (size_t)(m0 + lr) * 2048 + lu * 8;
    const __nv_bfloat16* Alp = Al + (size_t)(m0 + lr) * 2048 + lu * 8;
    const __nv_bfloat16* Bhp = Bh + (size_t)(n0 + lr) * 2048 + lu * 8;
    const __nv_bfloat16* Blp = Bl + (size_t)(n0 + lr) * 2048 + lu * 8;

    float acc[4][4][4] = {};

    // -------- prologue: prefetch stages 0,1 --------
#pragma unroll
    for (int s = 0; s < STAGES - 1; s++) {
        const uint32_t st = sb + s * STG_BYTES;
        const int k0 = s * BK;
        CP16(st + OFF_AH + sw0,        Ahp + k0);
        CP16(st + OFF_AH + sw0 + 4096, Ahp + k0 + (size_t)64 * 2048);
        CP16(st + OFF_AL + sw0,        Alp + k0);
        CP16(st + OFF_AL + sw0 + 4096, Alp + k0 + (size_t)64 * 2048);
        CP16(st + OFF_BH + sw0,        Bhp + k0);
        CP16(st + OFF_BH + sw0 + 4096, Bhp + k0 + (size_t)64 * 2048);
        CP16(st + OFF_BL + sw0,        Blp + k0);
        CP16(st + OFF_BL + sw0 + 4096, Blp + k0 + (size_t)64 * 2048);
        CP_COMMIT();
    }

    int cs = 0, ls = STAGES - 1;
    for (int it = 0; it < NIT; it++) {
        CP_WAIT(STAGES - 2);
        __syncthreads();
        const uint32_t st = sb + cs * STG_BYTES;
#pragma unroll
        for (int ks = 0; ks < 2; ks++) {
            // --- hi fragments ---
            uint32_t ah[4][4];
#pragma unroll
            for (int mt = 0; mt < 4; mt++)
                LDMX4(ah[mt], st + OFF_AH + aoff[mt] + (uint32_t)(((2 * ks + au) ^ arx[mt]) << 4));
            uint32_t bb[2][4];
#pragma unroll
            for (int p = 0; p < 2; p++)
                LDMX4(bb[p], st + boff[p] + (uint32_t)(((2 * ks + bu) ^ brx[p]) << 4));
            // Ah * Bh
#pragma unroll
            for (int mt = 0; mt < 4; mt++)
#pragma unroll
                for (int nt = 0; nt < 4; nt++)
                    MMA_BF16(acc[mt][nt], ah[mt], bb[nt >> 1][(nt & 1) * 2], bb[nt >> 1][(nt & 1) * 2 + 1]);
            // Al * Bh
            {
                uint32_t al[4][4];
#pragma unroll
                for (int mt = 0; mt < 4; mt++)
                    LDMX4(al[mt], st + OFF_AL + aoff[mt] + (uint32_t)(((2 * ks + au) ^ arx[mt]) << 4));
#pragma unroll
                for (int mt = 0; mt < 4; mt++)
#pragma unroll
                    for (int nt = 0; nt < 4; nt++)
                        MMA_BF16(acc[mt][nt], al[mt], bb[nt >> 1][(nt & 1) * 2], bb[nt >> 1][(nt & 1) * 2 + 1]);
            }
            // Ah * Bl (reuse bb regs)
#pragma unroll
            for (int p = 0; p < 2; p++)
                LDMX4(bb[p], st + boff[p] + 8192u + (uint32_t)(((2 * ks + bu) ^ brx[p]) << 4));
#pragma unroll
            for (int mt = 0; mt < 4; mt++)
#pragma unroll
                for (int nt = 0; nt < 4; nt++)
                    MMA_BF16(acc[mt][nt], ah[mt], bb[nt >> 1][(nt & 1) * 2], bb[nt >> 1][(nt & 1) * 2 + 1]);
        }
        const int nx = it + STAGES - 1;
        if (nx < NIT) {
            const uint32_t st2 = sb + ls * STG_BYTES;
            const int k0 = nx * BK;
            CP16(st2 + OFF_AH + sw0,        Ahp + k0);
            CP16(st2 + OFF_AH + sw0 + 4096, Ahp + k0 + (size_t)64 * 2048);
            CP16(st2 + OFF_AL + sw0,        Alp + k0);
            CP16(st2 + OFF_AL + sw0 + 4096, Alp + k0 + (size_t)64 * 2048);
            CP16(st2 + OFF_BH + sw0,        Bhp + k0);
            CP16(st2 + OFF_BH + sw0 + 4096, Bhp + k0 + (size_t)64 * 2048);
            CP16(st2 + OFF_BL + sw0,        Blp + k0);
            CP16(st2 + OFF_BL + sw0 + 4096, Blp + k0 + (size_t)64 * 2048);
            CP_COMMIT();
        }
        if (++cs == STAGES) cs = 0;
        if (++ls == STAGES) ls = 0;
    }

    // -------- epilogue --------
    const int g = lane >> 2, t = lane & 3;
#pragma unroll
    for (int mt = 0; mt < 4; mt++) {
#pragma unroll
        for (int nt = 0; nt < 4; nt++) {
            const int rm = m0 + wm + mt * 16 + g;
            const int cn = n0 + wn + nt * 8 + 2 * t;
            const float b0 = bias[cn], b1 = bias[cn + 1];
            float v0 = acc[mt][nt][0] + b0;
            float v1 = acc[mt][nt][1] + b1;
            float v2 = acc[mt][nt][2] + b0;
            float v3 = acc[mt][nt][3] + b1;
            if (ACT == 1) {
                v0 = v0 > 0.f ? v0 : (expf(v0) - 1.f);
                v1 = v1 > 0.f ? v1 : (expf(v1) - 1.f);
                v2 = v2 > 0.f ? v2 : (expf(v2) - 1.f);
                v3 = v3 > 0.f ? v3 : (expf(v3) - 1.f);
            } else if (ACT == 2) {
                v0 = v0 / (1.f + expf(-v0));
                v1 = v1 / (1.f + expf(-v1));
                v2 = v2 / (1.f + expf(-v2));
                v3 = v3 / (1.f + expf(-v3));
            }
            *(float2*)(C + (size_t)rm * 2048 + cn) = make_float2(v0, v1);
            *(float2*)(C + (size_t)(rm + 8) * 2048 + cn) = make_float2(v2, v3);
        }
    }
}

// ---------------------------------------------------------------------------
// prep kernels
// ---------------------------------------------------------------------------
__global__ void split_kernel(const float* __restrict__ x,
                             __nv_bfloat16* __restrict__ h, __nv_bfloat16* __restrict__ l, int n4) {
    int i = blockIdx.x * blockDim.x + threadIdx.x;
    if (i >= n4) return;
    float4 v = ((const float4*)x)[i];
    __nv_bfloat16 h0 = __float2bfloat16(v.x), h1 = __float2bfloat16(v.y);
    __nv_bfloat16 h2 = __float2bfloat16(v.z), h3 = __float2bfloat16(v.w);
    __nv_bfloat162* hp = (__nv_bfloat162*)h;
    __nv_bfloat162* lp = (__nv_bfloat162*)l;
    hp[i * 2 + 0] = __nv_bfloat162(h0, h1);
    hp[i * 2 + 1] = __nv_bfloat162(h2, h3);
    lp[i * 2 + 0] = __nv_bfloat162(__float2bfloat16(v.x - __bfloat162float(h0)),
                                   __float2bfloat16(v.y - __bfloat162float(h1)));
    lp[i * 2 + 1] = __nv_bfloat162(__float2bfloat16(v.z - __bfloat162float(h2)),
                                   __float2bfloat16(v.w - __bfloat162float(h3)));
}

// W[K,N] fp32 -> T[N,K] bf16 hi/lo (K=N=2048)
__global__ void tsplit_kernel(const float* __restrict__ W,
                              __nv_bfloat16* __restrict__ Th, __nv_bfloat16* __restrict__ Tl) {
    __shared__ float tile[32][33];
    const int k0 = blockIdx.y * 32, n0 = blockIdx.x * 32;
    const int tx = threadIdx.x, ty = threadIdx.y;
#pragma unroll
    for (int i = 0; i < 32; i += 8)
        tile[ty + i][tx] = W[(size_t)(k0 + ty + i) * 2048 + n0 + tx];
    __syncthreads();
#pragma unroll
    for (int i = 0; i < 32; i += 8) {
        float v = tile[tx][ty + i];
        __nv_bfloat16 hv = __float2bfloat16(v);
        size_t o = (size_t)(n0 + ty + i) * 2048 + k0 + tx;
        Th[o] = hv;
        Tl[o] = __float2bfloat16(v - __bfloat162float(hv));
    }
}

// ---------------------------------------------------------------------------
// kv = q^T v per (b,h), split over sequence (fp32 SIMT)
// ---------------------------------------------------------------------------
__global__ void kv_kernel() {
    __shared__ float qs[16][128];
    __shared__ float vs[16][128];
    const int bh = blockIdx.x;
    const int b = bh / HEADS, h = bh % HEADS;
    const int split = blockIdx.y;
    const int chunk = SEQ / SPLITS;          // 512
    const int n0 = split * chunk;
    const int tid = threadIdx.x;
    const int tx = tid & 15, ty = tid >> 4;
    const size_t base = (size_t)(b * SEQ) * HD + h * DHd;

    float acc[8][8] = {};
    for (int nt = 0; nt < chunk; nt += 16) {
#pragma unroll
        for (int l = 0; l < 2; l++) {
            const int idx = tid + l * 256;
            const int r = idx >> 5;
            const int c = (idx & 31) * 4;
            const size_t off = base + (size_t)(n0 + nt + r) * HD + c;
            *(float4*)&qs[r][c] = *(const float4*)(g_q + off);
            *(float4*)&vs[r][c] = *(const float4*)(g_v + off);
        }
        __syncthreads();
#pragma unroll
        for (int kk = 0; kk < 16; kk++) {
            float rq[8], rv[8];
#pragma unroll
            for (int i = 0; i < 8; i++) rq[i] = qs[kk][ty * 8 + i];
#pragma unroll
            for (int j = 0; j < 8; j++) rv[j] = vs[kk][tx * 8 + j];
#pragma unroll
            for (int i = 0; i < 8; i++)
#pragma unroll
                for (int j = 0; j < 8; j++)
                    acc[i][j] += rq[i] * rv[j];
        }
        __syncthreads();
    }
    float* kvp = g_kv + ((size_t)split * Bn * HEADS + bh) * DHd * DHd;
#pragma unroll
    for (int i = 0; i < 8; i++)
#pragma unroll
        for (int j = 0; j < 8; j++)
            kvp[(ty * 8 + i) * DHd + tx * 8 + j] = acc[i][j];
}

// ---------------------------------------------------------------------------
// out = q @ kv per (b,h) (fp32 SIMT, sums SPLITS slices)
// ---------------------------------------------------------------------------
__global__ void out_kernel() {
    __shared__ float As[16][64];
    __shared__ float Bs[16][128];
    const int m0 = blockIdx.x * 64;
    const int h = blockIdx.y;
    const int b = m0 / SEQ;
    const int tid = threadIdx.x;
    const int tx = tid & 15, ty = tid >> 4;
    const size_t kvoff = (size_t)(b * HEADS + h) * DHd * DHd;
    const size_t kvstride = (size_t)Bn * HEADS * DHd * DHd;

    float acc[4][8] = {};
    const int a_r = tid >> 2;
    const int a_s = (tid & 3) * 4;

    for (int k0 = 0; k0 < DHd; k0 += 16) {
        float4 av = *(const float4*)(g_q + (size_t)(m0 + a_r) * HD + h * DHd + k0 + a_s);
        As[a_s + 0][a_r] = av.x;
        As[a_s + 1][a_r] = av.y;
        As[a_s + 2][a_r] = av.z;
        As[a_s + 3][a_r] = av.w;
#pragma unroll
        for (int l = 0; l < 2; l++) {
            const int idx = tid + l * 256;
            const int r = idx >> 5;
            const int c = (idx & 31) * 4;
            const size_t boff = kvoff + (size_t)(k0 + r) * DHd + c;
            float sx = 0.f, sy = 0.f, sz = 0.f, sw = 0.f;
#pragma unroll
            for (int sp = 0; sp < SPLITS; sp++) {
                float4 s0 = *(const float4*)(g_kv + boff + (size_t)sp * kvstride);
                sx += s0.x; sy += s0.y; sz += s0.z; sw += s0.w;
            }
            Bs[r][c + 0] = sx; Bs[r][c + 1] = sy; Bs[r][c + 2] = sz; Bs[r][c + 3] = sw;
        }
        __syncthreads();
#pragma unroll
        for (int kk = 0; kk < 16; kk++) {
            float ra[4], rb[8];
#pragma unroll
            for (int i = 0; i < 4; i++) ra[i] = As[kk][ty * 4 + i];
#pragma unroll
            for (int j = 0; j < 8; j++) rb[j] = Bs[kk][tx * 8 + j];
#pragma unroll
            for (int i = 0; i < 4; i++)
#pragma unroll
                for (int j = 0; j < 8; j++)
                    acc[i][j] += ra[i] * rb[j];
        }
        __syncthreads();
    }
#pragma unroll
    for (int i = 0; i < 4; i++)
#pragma unroll
        for (int j = 0; j < 8; j++)
            g_o[(size_t)(m0 + ty * 4 + i) * HD + h * DHd + tx * 8 + j] = acc[i][j];
}

// ---------------------------------------------------------------------------
// LayerNorm over HD, * gate u, emit bf16 hi/lo for final GEMM
// ---------------------------------------------------------------------------
__global__ void ln_mul_kernel(const float* __restrict__ lng, const float* __restrict__ lnb) {
    __shared__ float buf[HD];
    __shared__ float red[256];
    const int row = blockIdx.x;
    const int tid = threadIdx.x;
    const float* orow = g_o + (size_t)row * HD;
    const float* urow = g_u + (size_t)row * HD;

    float s = 0.f;
    for (int c = tid; c < HD; c += 256) { float v = orow[c]; buf[c] = v; s += v; }
    red[tid] = s; __syncthreads();
    for (int off = 128; off; off >>= 1) { if (tid < off) red[tid] += red[tid + off]; __syncthreads(); }
    const float mean = red[0] * (1.f / HD);
    __syncthreads();

    float s2 = 0.f;
    for (int c = tid; c < HD; c += 256) { float d = buf[c] - mean; s2 += d * d; }
    red[tid] = s2; __syncthreads();
    for (int off = 128; off; off >>= 1) { if (tid < off) red[tid] += red[tid + off]; __syncthreads(); }
    const float rstd = rsqrtf(red[0] * (1.f / HD) + 1e-5f);

    for (int c = tid; c < HD; c += 256) {
        float v = ((buf[c] - mean) * rstd * lng[c] + lnb[c]) * urow[c];
        __nv_bfloat16 hv = __float2bfloat16(v);
        g_lnh[(size_t)row * HD + c] = hv;
        g_lnl[(size_t)row * HD + c] = __float2bfloat16(v - __bfloat162float(hv));
    }
}

// ---------------------------------------------------------------------------
// launch
// ---------------------------------------------------------------------------
extern "C" void kernel_launch(void* const* d_in, const int* in_sizes, int n_in,
                              void* d_out, int out_size) {
    const float* x   = (const float*)d_in[0];
    const float* Wqk = (const float*)d_in[1];
    const float* bqk = (const float*)d_in[2];
    const float* Wv  = (const float*)d_in[3];
    const float* bv  = (const float*)d_in[4];
    const float* Wu  = (const float*)d_in[5];
    const float* bu  = (const float*)d_in[6];
    const float* Wo  = (const float*)d_in[7];
    const float* bo  = (const float*)d_in[8];
    const float* lng = (const float*)d_in[9];
    const float* lnb = (const float*)d_in[10];
    float* out = (float*)d_out;

    float *pq, *pv, *pu;
    __nv_bfloat16 *pxh, *pxl, *plnh, *plnl;
    __nv_bfloat16 *pwqkh, *pwqkl, *pwvh, *pwvl, *pwuh, *pwul, *pwoh, *pwol;
    cudaGetSymbolAddress((void**)&pq, g_q);
    cudaGetSymbolAddress((void**)&pv, g_v);
    cudaGetSymbolAddress((void**)&pu, g_u);
    cudaGetSymbolAddress((void**)&pxh, g_xh);
    cudaGetSymbolAddress((void**)&pxl, g_xl);
    cudaGetSymbolAddress((void**)&plnh, g_lnh);
    cudaGetSymbolAddress((void**)&plnl, g_lnl);
    cudaGetSymbolAddress((void**)&pwqkh, g_wqkh);
    cudaGetSymbolAddress((void**)&pwqkl, g_wqkl);
    cudaGetSymbolAddress((void**)&pwvh, g_wvh);
    cudaGetSymbolAddress((void**)&pwvl, g_wvl);
    cudaGetSymbolAddress((void**)&pwuh, g_wuh);
    cudaGetSymbolAddress((void**)&pwul, g_wul);
    cudaGetSymbolAddress((void**)&pwoh, g_woh);
    cudaGetSymbolAddress((void**)&pwol, g_wol);

    cudaFuncSetAttribute(gemm_bf16_3p<0>, cudaFuncAttributeMaxDynamicSharedMemorySize, GEMM_SMEM);
    cudaFuncSetAttribute(gemm_bf16_3p<1>, cudaFuncAttributeMaxDynamicSharedMemorySize, GEMM_SMEM);
    cudaFuncSetAttribute(gemm_bf16_3p<2>, cudaFuncAttributeMaxDynamicSharedMemorySize, GEMM_SMEM);

    // prep: split x; transpose+split weights
    {
        int n4 = MR * Ein / 4;
        split_kernel<<<(n4 + 255) / 256, 256>>>(x, pxh, pxl, n4);
        dim3 tb(32, 8), tg(64, 64);
        tsplit_kernel<<<tg, tb>>>(Wqk, pwqkh, pwqkl);
        tsplit_kernel<<<tg, tb>>>(Wv,  pwvh,  pwvl);
        tsplit_kernel<<<tg, tb>>>(Wu,  pwuh,  pwul);
        tsplit_kernel<<<tg, tb>>>(Wo,  pwoh,  pwol);
    }

    dim3 ggrid(HD / BN, MR / BM);    // (16, 128)

    // q = elu(x@Wqk + bqk); v = silu(x@Wv + bv); u = silu(x@Wu + bu)
    gemm_bf16_3p<1><<<ggrid, 256, GEMM_SMEM>>>(pxh, pxl, pwqkh, pwqkl, bqk, pq);
    gemm_bf16_3p<2><<<ggrid, 256, GEMM_SMEM>>>(pxh, pxl, pwvh,  pwvl,  bv,  pv);
    gemm_bf16_3p<2><<<ggrid, 256, GEMM_SMEM>>>(pxh, pxl, pwuh,  pwul,  bu,  pu);

    // linear attention
    kv_kernel<<<dim3(Bn * HEADS, SPLITS), 256>>>();
    out_kernel<<<dim3(MR / 64, HEADS), 256>>>();

    // LN * gate -> bf16 hi/lo
    ln_mul_kernel<<<MR, 256>>>(lng, lnb);

    // y = ln_out @ Wo + bo
    gemm_bf16_3p<0><<<ggrid, 256, GEMM_SMEM>>>(plnh, plnl, pwoh, pwol, bo, out);
}